// round 2
// baseline (speedup 1.0000x reference)
#include <cuda_runtime.h>
#include <math.h>

#define BB 8192
#define DD 1024
#define EE 8
#define NQv 8
#define NLv 2
#define HHv 1024

// ---------------- scratch (static device globals: no allocation) ----------------
__device__ float g_X1[(size_t)BB * DD];        // inter-block activations (32MB)
__device__ float g_H[(size_t)BB * 2 * HHv];    // gated, scaled hidden per (row,slot) (64MB)
__device__ float g_OUT[(size_t)BB * DD];       // residual + bias + GEMM accumulator (32MB)
__device__ int   g_cnt[EE];
__device__ int   g_list[EE * BB];              // entries encode row*2+slot

// ---------------- reset ----------------
__global__ void k_reset() {
    if (threadIdx.x < EE) g_cnt[threadIdx.x] = 0;
}

// ---------------- fused gate + qsim + hidden ----------------
__global__ __launch_bounds__(256) void k_gate_qsim(
    const float* __restrict__ Xext,
    const float* __restrict__ gW, const float* __restrict__ gb,
    const float* __restrict__ qp, const float* __restrict__ rW,
    const float* __restrict__ rb, const float* __restrict__ b2,
    int blk)
{
    __shared__ float xrow[DD];
    __shared__ float2 st[256];
    __shared__ float2 m00[NQv], m01[NQv], m10[NQv], m11[NQv];
    __shared__ float logits[EE];
    __shared__ float cq[NQv], sq[NQv];
    __shared__ float qv[2][NQv];
    __shared__ int   sel[2];
    __shared__ float wsel[2];

    const float* X = (blk == 0) ? Xext : g_X1;
    int b = blockIdx.x;
    int tid = threadIdx.x;

    const float* xr = X + (size_t)b * DD;
    for (int d = tid; d < DD; d += 256) xrow[d] = xr[d];
    if (tid < EE) logits[tid] = 0.f;
    if (tid < 2 * NQv) qv[tid >> 3][tid & 7] = 0.f;
    __syncthreads();

    // ---- gate logits ----
    float acc[EE];
    #pragma unroll
    for (int e = 0; e < EE; e++) acc[e] = 0.f;
    for (int d = tid; d < DD; d += 256) {
        float xv = xrow[d];
        const float* gwr = gW + ((size_t)blk * DD + d) * EE;
        #pragma unroll
        for (int e = 0; e < EE; e++) acc[e] += xv * gwr[e];
    }
    #pragma unroll
    for (int e = 0; e < EE; e++) {
        float v = acc[e];
        #pragma unroll
        for (int o = 16; o > 0; o >>= 1) v += __shfl_xor_sync(0xffffffffu, v, o);
        if ((tid & 31) == 0) atomicAdd(&logits[e], v);
    }
    __syncthreads();

    if (tid == 0) {
        float l[EE], mx = -1e30f;
        #pragma unroll
        for (int e = 0; e < EE; e++) { l[e] = logits[e] + gb[blk * EE + e]; mx = fmaxf(mx, l[e]); }
        float sum = 0.f;
        #pragma unroll
        for (int e = 0; e < EE; e++) { l[e] = expf(l[e] - mx); sum += l[e]; }
        float inv = 1.f / sum;
        #pragma unroll
        for (int e = 0; e < EE; e++) l[e] *= inv;
        // top-2, first-occurrence tie-break (matches lax.top_k)
        int i0 = 0;
        #pragma unroll
        for (int e = 1; e < EE; e++) if (l[e] > l[i0]) i0 = e;
        int i1 = (i0 == 0) ? 1 : 0;
        #pragma unroll
        for (int e = 0; e < EE; e++) if (e != i1 && e != i0 && l[e] > l[i1]) i1 = e;
        float p0 = l[i0], p1 = l[i1];
        // softmax over the two (already-softmaxed) probabilities — exact per reference
        float w1 = 1.f / (1.f + expf(p0 - p1));
        float w0 = 1.f - w1;
        sel[0] = i0; sel[1] = i1; wsel[0] = w0; wsel[1] = w1;
        int pos0 = atomicAdd(&g_cnt[i0], 1); g_list[i0 * BB + pos0] = b * 2 + 0;
        int pos1 = atomicAdd(&g_cnt[i1], 1); g_list[i1 * BB + pos1] = b * 2 + 1;
    }
    if (tid < NQv) {
        float a = 0.5f * xrow[tid];
        cq[tid] = cosf(a);
        sq[tid] = sinf(a);
    }
    __syncthreads();

    // ---- init accumulator: residual + weighted expert biases ----
    {
        int e0 = sel[0], e1 = sel[1];
        float w0 = wsel[0], w1 = wsel[1];
        const float* b2a = b2 + ((size_t)blk * EE + e0) * DD;
        const float* b2b = b2 + ((size_t)blk * EE + e1) * DD;
        for (int n = tid; n < DD; n += 256)
            g_OUT[(size_t)b * DD + n] = xrow[n] + w0 * b2a[n] + w1 * b2b[n];
    }

    // ---- quantum sim per selected expert ----
    for (int s = 0; s < 2; s++) {
        int e = sel[s];
        // initial product state (real)
        {
            float v = 1.f;
            #pragma unroll
            for (int q = 0; q < NQv; q++)
                v *= ((tid >> (NQv - 1 - q)) & 1) ? sq[q] : cq[q];
            st[tid] = make_float2(v, 0.f);
        }
        const float* qpe = qp + ((size_t)(blk * EE + e) * NLv) * NQv * 3;
        for (int l = 0; l < NLv; l++) {
            __syncthreads();
            if (tid < NQv) {
                const float* p = qpe + (l * NQv + tid) * 3;
                float phi = p[0], th = p[1], om = p[2];
                float c, sn; sincosf(0.5f * th, &sn, &c);
                float sa, ca; sincosf(0.5f * (phi + om), &sa, &ca);
                float sb, cb; sincosf(0.5f * (phi - om), &sb, &cb);
                m00[tid] = make_float2(ca * c, -sa * c);
                m11[tid] = make_float2(ca * c,  sa * c);
                m01[tid] = make_float2(-cb * sn, -sb * sn);
                m10[tid] = make_float2( cb * sn, -sb * sn);
            }
            __syncthreads();
            #pragma unroll
            for (int q = 0; q < NQv; q++) {
                int pb = NQv - 1 - q;
                if (tid < 128) {
                    int i0 = ((tid >> pb) << (pb + 1)) | (tid & ((1 << pb) - 1));
                    int i1 = i0 | (1 << pb);
                    float2 a0 = st[i0], a1 = st[i1];
                    float2 M00 = m00[q], M01 = m01[q], M10 = m10[q], M11 = m11[q];
                    float2 n0, n1;
                    n0.x = M00.x * a0.x - M00.y * a0.y + M01.x * a1.x - M01.y * a1.y;
                    n0.y = M00.x * a0.y + M00.y * a0.x + M01.x * a1.y + M01.y * a1.x;
                    n1.x = M10.x * a0.x - M10.y * a0.y + M11.x * a1.x - M11.y * a1.y;
                    n1.y = M10.x * a0.y + M10.y * a0.x + M11.x * a1.y + M11.y * a1.x;
                    st[i0] = n0; st[i1] = n1;
                }
                __syncthreads();
            }
            // CNOT chain q=0..6 collapsed into one permutation:
            // source(i) = sigma_{0,1}(sigma_{1,2}(...sigma_{6,7}(i)))
            {
                int j = tid;
                #pragma unroll
                for (int q = NQv - 2; q >= 0; q--) {
                    int pc = NQv - 1 - q;      // control bit position
                    int pt = NQv - 2 - q;      // target bit position
                    j ^= ((j >> pc) & 1) << pt;
                }
                float2 v = st[j];
                __syncthreads();
                st[tid] = v;
            }
        }
        __syncthreads();
        // Z expectations
        {
            float p = st[tid].x * st[tid].x + st[tid].y * st[tid].y;
            #pragma unroll
            for (int k = 0; k < NQv; k++) {
                float v = ((tid >> (NQv - 1 - k)) & 1) ? -p : p;
                #pragma unroll
                for (int o = 16; o > 0; o >>= 1) v += __shfl_xor_sync(0xffffffffu, v, o);
                if ((tid & 31) == 0) atomicAdd(&qv[s][k], v);
            }
        }
        __syncthreads();
    }

    // ---- hidden: h = relu(q @ rW + rb) * gate_weight ----
    #pragma unroll
    for (int s = 0; s < 2; s++) {
        int e = sel[s];
        float w = wsel[s];
        float qr[NQv];
        #pragma unroll
        for (int j = 0; j < NQv; j++) qr[j] = qv[s][j];
        const float* rWe = rW + ((size_t)(blk * EE + e)) * NQv * HHv;
        const float* rbe = rb + ((size_t)(blk * EE + e)) * HHv;
        float* Hd = g_H + ((size_t)b * 2 + s) * HHv;
        for (int n = tid; n < HHv; n += 256) {
            float a = rbe[n];
            #pragma unroll
            for (int j = 0; j < NQv; j++) a += qr[j] * rWe[j * HHv + n];
            Hd[n] = fmaxf(a, 0.f) * w;
        }
    }
}

// ---------------- grouped expert GEMM: OUT += H_gathered @ w2[e] ----------------
__global__ __launch_bounds__(256) void k_moe_gemm(const float* __restrict__ w2, int blk)
{
    int e = blockIdx.z;
    int n_e = g_cnt[e];
    int m0 = blockIdx.y * 64;
    if (m0 >= n_e) return;
    int n0 = blockIdx.x * 64;

    __shared__ float As[16][68];
    __shared__ float Bs[16][64];
    __shared__ int   rows[64];

    int tid = threadIdx.x;
    if (tid < 64) {
        int m = m0 + tid;
        rows[tid] = (m < n_e) ? g_list[e * BB + m] : -1;
    }
    __syncthreads();

    const float* w2e = w2 + ((size_t)(blk * EE + e)) * HHv * DD;

    float accum[4][4];
    #pragma unroll
    for (int i = 0; i < 4; i++)
        #pragma unroll
        for (int j = 0; j < 4; j++) accum[i][j] = 0.f;

    int tr = (tid >> 4) * 4;
    int tc = (tid & 15) * 4;
    int la_m = tid >> 2;
    int la_k = (tid & 3) * 4;
    int lb_k = tid >> 4;
    int lb_n = (tid & 15) * 4;

    int rowA = rows[la_m];
    const float* Hrow = (rowA >= 0) ? (g_H + (size_t)rowA * HHv) : 0;

    for (int k0 = 0; k0 < HHv; k0 += 16) {
        float4 av = Hrow ? *(const float4*)(Hrow + k0 + la_k) : make_float4(0.f, 0.f, 0.f, 0.f);
        float4 bv = *(const float4*)(w2e + (size_t)(k0 + lb_k) * DD + n0 + lb_n);
        __syncthreads();
        As[la_k + 0][la_m] = av.x;
        As[la_k + 1][la_m] = av.y;
        As[la_k + 2][la_m] = av.z;
        As[la_k + 3][la_m] = av.w;
        *(float4*)&Bs[lb_k][lb_n] = bv;
        __syncthreads();
        #pragma unroll
        for (int k = 0; k < 16; k++) {
            float a0 = As[k][tr], a1 = As[k][tr + 1], a2 = As[k][tr + 2], a3 = As[k][tr + 3];
            float4 bq = *(float4*)&Bs[k][tc];
            accum[0][0] += a0 * bq.x; accum[0][1] += a0 * bq.y; accum[0][2] += a0 * bq.z; accum[0][3] += a0 * bq.w;
            accum[1][0] += a1 * bq.x; accum[1][1] += a1 * bq.y; accum[1][2] += a1 * bq.z; accum[1][3] += a1 * bq.w;
            accum[2][0] += a2 * bq.x; accum[2][1] += a2 * bq.y; accum[2][2] += a2 * bq.z; accum[2][3] += a2 * bq.w;
            accum[3][0] += a3 * bq.x; accum[3][1] += a3 * bq.y; accum[3][2] += a3 * bq.z; accum[3][3] += a3 * bq.w;
        }
    }

    #pragma unroll
    for (int i = 0; i < 4; i++) {
        int rs = rows[tr + i];
        if (rs < 0) continue;
        float* outp = g_OUT + (size_t)(rs >> 1) * DD + n0 + tc;
        atomicAdd(outp + 0, accum[i][0]);
        atomicAdd(outp + 1, accum[i][1]);
        atomicAdd(outp + 2, accum[i][2]);
        atomicAdd(outp + 3, accum[i][3]);
    }
}

// ---------------- layernorm ----------------
__device__ __forceinline__ float blockReduceSum(float v, float* red)
{
    __syncthreads();
    int lane = threadIdx.x & 31;
    int w = threadIdx.x >> 5;
    #pragma unroll
    for (int o = 16; o > 0; o >>= 1) v += __shfl_xor_sync(0xffffffffu, v, o);
    if (lane == 0) red[w] = v;
    __syncthreads();
    float r = (lane < 8) ? red[lane] : 0.f;
    #pragma unroll
    for (int o = 4; o > 0; o >>= 1) r += __shfl_xor_sync(0xffffffffu, r, o);
    return r;  // valid in lane groups; broadcast below
}

__global__ __launch_bounds__(256) void k_ln(
    const float* __restrict__ gam, const float* __restrict__ bet,
    float* __restrict__ Yext, int blk)
{
    __shared__ float red[32];
    __shared__ float bc[2];
    int b = blockIdx.x, tid = threadIdx.x;
    float* Y = (blk == 0) ? g_X1 : Yext;

    const float* y = g_OUT + (size_t)b * DD;
    float v[4];
    float s = 0.f;
    #pragma unroll
    for (int i = 0; i < 4; i++) { v[i] = y[tid + 256 * i]; s += v[i]; }
    float tot = blockReduceSum(s, red);
    if (tid == 0) bc[0] = tot;
    __syncthreads();
    float mu = bc[0] * (1.f / 1024.f);

    float s2 = 0.f;
    #pragma unroll
    for (int i = 0; i < 4; i++) { float d = v[i] - mu; s2 += d * d; }
    float tot2 = blockReduceSum(s2, red);
    if (tid == 0) bc[1] = tot2;
    __syncthreads();
    float inv = 1.f / sqrtf(bc[1] * (1.f / 1024.f) + 1e-5f);

    #pragma unroll
    for (int i = 0; i < 4; i++) {
        int n = tid + 256 * i;
        Y[(size_t)b * DD + n] = (v[i] - mu) * inv * gam[blk * DD + n] + bet[blk * DD + n];
    }
}

// ---------------- launch ----------------
extern "C" void kernel_launch(void* const* d_in, const int* in_sizes, int n_in,
                              void* d_out, int out_size)
{
    (void)in_sizes; (void)n_in; (void)out_size;
    const float* x  = (const float*)d_in[0];
    const float* gW = (const float*)d_in[1];
    const float* gb = (const float*)d_in[2];
    const float* qp = (const float*)d_in[3];
    const float* rW = (const float*)d_in[4];
    const float* rb = (const float*)d_in[5];
    const float* w2 = (const float*)d_in[6];
    const float* b2 = (const float*)d_in[7];
    const float* lg = (const float*)d_in[8];
    const float* lb = (const float*)d_in[9];
    float* out = (float*)d_out;

    for (int blk = 0; blk < 2; blk++) {
        k_reset<<<1, 32>>>();
        k_gate_qsim<<<BB, 256>>>(x, gW, gb, qp, rW, rb, b2, blk);
        dim3 g2(DD / 64, BB / 64, EE);
        k_moe_gemm<<<g2, 256>>>(w2, blk);
        k_ln<<<BB, 256>>>(lg, lb, out, blk);
    }
}